// round 2
// baseline (speedup 1.0000x reference)
#include <cuda_runtime.h>
#include <math.h>

#define SEQ 4096
#define DM 1024
#define NH 16
#define HD 64
#define WIN 512

// Scratch (allocation-free rule: __device__ globals)
__device__ float g_qkv[SEQ * 3 * DM];        // 48 MB
__device__ float g_q[NH * SEQ * HD];         // 16 MB
__device__ float g_k[NH * SEQ * HD];         // 16 MB
__device__ float g_v[NH * SEQ * HD];         // 16 MB
__device__ float g_att[SEQ * DM];            // 16 MB

// ---------------------------------------------------------------------------
// SGEMM: C[M,N] = A[M,K] @ B[K,N], fp32, BM=BN=128, BK=16, 256 threads, 8x8/thr
// M%128==0, N%128==0, K%16==0 (holds for all our shapes)
// ---------------------------------------------------------------------------
__global__ __launch_bounds__(256) void sgemm_kernel(
    const float* __restrict__ A, const float* __restrict__ B,
    float* __restrict__ C, int M, int N, int K)
{
    __shared__ float As[16][128];   // transposed A tile
    __shared__ float Bs[16][128];

    const int bx = blockIdx.x;      // N tile
    const int by = blockIdx.y;      // M tile
    const int tid = threadIdx.x;

    // A tile load mapping: 128 rows x 16 cols -> 128x4 float4 loads, 2 per thread
    const int rowA = tid >> 2;            // 0..63
    const int colA = (tid & 3) * 4;       // 0,4,8,12
    // B tile load mapping: 16 rows x 128 cols -> 16x32 float4 loads, 2 per thread
    const int rowB = tid >> 5;            // 0..7
    const int colB = (tid & 31) * 4;      // 0..124

    const int tr = (tid >> 4) * 8;        // thread row base in tile (0..120)
    const int tc = (tid & 15) * 8;        // thread col base in tile

    float acc[8][8];
#pragma unroll
    for (int u = 0; u < 8; u++)
#pragma unroll
        for (int v = 0; v < 8; v++) acc[u][v] = 0.f;

    const float* Abase = A + (size_t)(by * 128) * K;
    const float* Bbase = B + bx * 128;

    for (int kt = 0; kt < K; kt += 16) {
        float4 a0 = *(const float4*)(Abase + (size_t)rowA        * K + kt + colA);
        float4 a1 = *(const float4*)(Abase + (size_t)(rowA + 64) * K + kt + colA);
        float4 b0 = *(const float4*)(Bbase + (size_t)(kt + rowB)     * N + colB);
        float4 b1 = *(const float4*)(Bbase + (size_t)(kt + rowB + 8) * N + colB);

        __syncthreads();   // previous tile fully consumed
        As[colA + 0][rowA] = a0.x;  As[colA + 1][rowA] = a0.y;
        As[colA + 2][rowA] = a0.z;  As[colA + 3][rowA] = a0.w;
        As[colA + 0][rowA + 64] = a1.x;  As[colA + 1][rowA + 64] = a1.y;
        As[colA + 2][rowA + 64] = a1.z;  As[colA + 3][rowA + 64] = a1.w;
        *(float4*)(&Bs[rowB][colB])     = b0;
        *(float4*)(&Bs[rowB + 8][colB]) = b1;
        __syncthreads();

#pragma unroll
        for (int kk = 0; kk < 16; kk++) {
            float ra[8], rb[8];
#pragma unroll
            for (int u = 0; u < 8; u++) ra[u] = As[kk][tr + u];
#pragma unroll
            for (int v = 0; v < 8; v++) rb[v] = Bs[kk][tc + v];
#pragma unroll
            for (int u = 0; u < 8; u++)
#pragma unroll
                for (int v = 0; v < 8; v++) acc[u][v] = fmaf(ra[u], rb[v], acc[u][v]);
        }
    }

    float* Cbase = C + (size_t)(by * 128 + tr) * N + bx * 128 + tc;
#pragma unroll
    for (int u = 0; u < 8; u++) {
        *(float4*)(Cbase + (size_t)u * N)     = make_float4(acc[u][0], acc[u][1], acc[u][2], acc[u][3]);
        *(float4*)(Cbase + (size_t)u * N + 4) = make_float4(acc[u][4], acc[u][5], acc[u][6], acc[u][7]);
    }
}

// ---------------------------------------------------------------------------
// RoPE + scatter: qkv[L, 3*DM] -> q,k (rotated), v (copied), head-major [h][L][64]
// One thread per (l, h, pair); pair index p in [0,32)
// ---------------------------------------------------------------------------
__global__ __launch_bounds__(256) void rope_scatter_kernel(const float* __restrict__ qkv)
{
    int idx = blockIdx.x * blockDim.x + threadIdx.x;
    if (idx >= SEQ * NH * 32) return;
    int p = idx & 31;
    int h = (idx >> 5) & (NH - 1);
    int l = idx >> 9;                 // / (32*NH)

    // inv_freq = 10000^(-2p/64); angle = l * inv_freq
    float inv_freq = powf(10000.0f, -(2.0f * (float)p) / 64.0f);
    float ang = (float)l * inv_freq;
    float s, c;
    sincosf(ang, &s, &c);

    const float* src = qkv + (size_t)l * (3 * DM);
    int col = h * HD + 2 * p;
    float q0 = src[col],          q1 = src[col + 1];
    float k0 = src[DM + col],     k1 = src[DM + col + 1];
    float v0 = src[2 * DM + col], v1 = src[2 * DM + col + 1];

    size_t dst = (size_t)(h * SEQ + l) * HD + 2 * p;
    g_q[dst]     = q0 * c - q1 * s;
    g_q[dst + 1] = q1 * c + q0 * s;
    g_k[dst]     = k0 * c - k1 * s;
    g_k[dst + 1] = k1 * c + k0 * s;
    g_v[dst]     = v0;
    g_v[dst + 1] = v1;
}

// ---------------------------------------------------------------------------
// Sliding-window causal attention.
// Block = 128 threads = 128 consecutive query rows of one head.
// Each thread: q[64] + o[64] in regs, online softmax with lazy rescale.
// K/V staged in smem tiles of 64 rows.
// ---------------------------------------------------------------------------
__global__ __launch_bounds__(128) void attn_kernel(
    const float* __restrict__ Q, const float* __restrict__ K,
    const float* __restrict__ V, float* __restrict__ O)
{
    __shared__ float Ks[64][64];
    __shared__ float Vs[64][64];

    const int h  = blockIdx.y;
    const int r0 = blockIdx.x * 128;
    const int i  = r0 + threadIdx.x;     // this thread's query row

    float qr[64];
    {
        const float4* qp = (const float4*)(Q + (size_t)(h * SEQ + i) * HD);
#pragma unroll
        for (int d = 0; d < 16; d++) ((float4*)qr)[d] = qp[d];
    }

    float m = -INFINITY, lsum = 0.f;
    float o[64];
#pragma unroll
    for (int d = 0; d < 64; d++) o[d] = 0.f;

    const int jlo = max(0, r0 - (WIN - 1));
    const int t0 = jlo >> 6;
    const int t1 = (r0 + 127) >> 6;

    for (int t = t0; t <= t1; t++) {
        __syncthreads();
        const float4* kb = (const float4*)(K + (size_t)(h * SEQ + t * 64) * HD);
        const float4* vb = (const float4*)(V + (size_t)(h * SEQ + t * 64) * HD);
#pragma unroll
        for (int u = 0; u < 8; u++) {
            int fidx = u * 128 + threadIdx.x;   // 0..1023 float4 slots
            int row = fidx >> 4, c4 = fidx & 15;
            ((float4*)Ks[row])[c4] = kb[fidx];
            ((float4*)Vs[row])[c4] = vb[fidx];
        }
        __syncthreads();

#pragma unroll 1
        for (int jj = 0; jj < 64; jj++) {
            int j = t * 64 + jj;
            if (j > i || (i - j) >= WIN) continue;

            float s0 = 0.f, s1 = 0.f, s2 = 0.f, s3 = 0.f;
#pragma unroll
            for (int d = 0; d < 64; d += 4) {
                s0 = fmaf(qr[d + 0], Ks[jj][d + 0], s0);
                s1 = fmaf(qr[d + 1], Ks[jj][d + 1], s1);
                s2 = fmaf(qr[d + 2], Ks[jj][d + 2], s2);
                s3 = fmaf(qr[d + 3], Ks[jj][d + 3], s3);
            }
            float s = ((s0 + s1) + (s2 + s3)) * 0.125f;

            float p;
            if (s > m) {
                float corr = __expf(m - s);   // exp(-inf)=0 handles first key
                m = s;
                lsum *= corr;
#pragma unroll
                for (int d = 0; d < 64; d++) o[d] *= corr;
                p = 1.0f;
            } else {
                p = __expf(s - m);
            }
            lsum += p;
#pragma unroll
            for (int d = 0; d < 64; d++) o[d] = fmaf(p, Vs[jj][d], o[d]);
        }
    }

    float inv = 1.0f / lsum;
    float* op = O + (size_t)i * DM + h * HD;
#pragma unroll
    for (int d = 0; d < 64; d++) o[d] *= inv;
#pragma unroll
    for (int d = 0; d < 16; d++) ((float4*)op)[d] = ((float4*)o)[d];
}

// ---------------------------------------------------------------------------
extern "C" void kernel_launch(void* const* d_in, const int* in_sizes, int n_in,
                              void* d_out, int out_size)
{
    const float* x     = (const float*)d_in[0];   // [1,4096,1024]
    const float* w_qkv = (const float*)d_in[1];   // [1024,3072]
    const float* w_out = (const float*)d_in[2];   // [1024,1024]
    float* out = (float*)d_out;                   // [1,4096,1024]

    float *p_qkv, *p_q, *p_k, *p_v, *p_att;
    cudaGetSymbolAddress((void**)&p_qkv, g_qkv);
    cudaGetSymbolAddress((void**)&p_q,   g_q);
    cudaGetSymbolAddress((void**)&p_k,   g_k);
    cudaGetSymbolAddress((void**)&p_v,   g_v);
    cudaGetSymbolAddress((void**)&p_att, g_att);

    // 1) qkv = x @ w_qkv   (4096 x 3072 x 1024)
    sgemm_kernel<<<dim3(3 * DM / 128, SEQ / 128), 256>>>(x, w_qkv, p_qkv, SEQ, 3 * DM, DM);

    // 2) RoPE + head-major scatter
    {
        int total = SEQ * NH * 32;
        rope_scatter_kernel<<<(total + 255) / 256, 256>>>(p_qkv);
    }

    // 3) sliding-window attention -> g_att in [L, DM] layout
    attn_kernel<<<dim3(SEQ / 128, NH), 128>>>(p_q, p_k, p_v, p_att);

    // 4) out = att @ w_out  (4096 x 1024 x 1024)
    sgemm_kernel<<<dim3(DM / 128, SEQ / 128), 256>>>(p_att, w_out, out, SEQ, DM, DM);
}

// round 4
// speedup vs baseline: 1.1236x; 1.1236x over previous
#include <cuda_runtime.h>
#include <math.h>

#define SEQ 4096
#define DM 1024
#define NH 16
#define HD 64
#define WIN 512

// Scratch (allocation-free rule: __device__ globals)
__device__ float g_qkv[SEQ * 3 * DM];
__device__ float g_q[NH * SEQ * HD];
__device__ float g_k[NH * SEQ * HD];
__device__ float g_v[NH * SEQ * HD];
__device__ float g_att[SEQ * DM];

// ---------------------------------------------------------------------------
// SGEMM: C[M,N] = A[M,K] @ B[K,N], fp32, BM=BN=128, BK=16, 256 threads, 8x8/thr
// ---------------------------------------------------------------------------
__global__ __launch_bounds__(256) void sgemm_kernel(
    const float* __restrict__ A, const float* __restrict__ B,
    float* __restrict__ C, int M, int N, int K)
{
    __shared__ float As[16][128];
    __shared__ float Bs[16][128];

    const int bx = blockIdx.x;
    const int by = blockIdx.y;
    const int tid = threadIdx.x;

    const int rowA = tid >> 2;
    const int colA = (tid & 3) * 4;
    const int rowB = tid >> 5;
    const int colB = (tid & 31) * 4;

    const int tr = (tid >> 4) * 8;
    const int tc = (tid & 15) * 8;

    float acc[8][8];
#pragma unroll
    for (int u = 0; u < 8; u++)
#pragma unroll
        for (int v = 0; v < 8; v++) acc[u][v] = 0.f;

    const float* Abase = A + (size_t)(by * 128) * K;
    const float* Bbase = B + bx * 128;

    for (int kt = 0; kt < K; kt += 16) {
        float4 a0 = *(const float4*)(Abase + (size_t)rowA        * K + kt + colA);
        float4 a1 = *(const float4*)(Abase + (size_t)(rowA + 64) * K + kt + colA);
        float4 b0 = *(const float4*)(Bbase + (size_t)(kt + rowB)     * N + colB);
        float4 b1 = *(const float4*)(Bbase + (size_t)(kt + rowB + 8) * N + colB);

        __syncthreads();
        As[colA + 0][rowA] = a0.x;  As[colA + 1][rowA] = a0.y;
        As[colA + 2][rowA] = a0.z;  As[colA + 3][rowA] = a0.w;
        As[colA + 0][rowA + 64] = a1.x;  As[colA + 1][rowA + 64] = a1.y;
        As[colA + 2][rowA + 64] = a1.z;  As[colA + 3][rowA + 64] = a1.w;
        *(float4*)(&Bs[rowB][colB])     = b0;
        *(float4*)(&Bs[rowB + 8][colB]) = b1;
        __syncthreads();

#pragma unroll
        for (int kk = 0; kk < 16; kk++) {
            float ra[8], rb[8];
#pragma unroll
            for (int u = 0; u < 8; u++) ra[u] = As[kk][tr + u];
#pragma unroll
            for (int v = 0; v < 8; v++) rb[v] = Bs[kk][tc + v];
#pragma unroll
            for (int u = 0; u < 8; u++)
#pragma unroll
                for (int v = 0; v < 8; v++) acc[u][v] = fmaf(ra[u], rb[v], acc[u][v]);
        }
    }

    float* Cbase = C + (size_t)(by * 128 + tr) * N + bx * 128 + tc;
#pragma unroll
    for (int u = 0; u < 8; u++) {
        *(float4*)(Cbase + (size_t)u * N)     = make_float4(acc[u][0], acc[u][1], acc[u][2], acc[u][3]);
        *(float4*)(Cbase + (size_t)u * N + 4) = make_float4(acc[u][4], acc[u][5], acc[u][6], acc[u][7]);
    }
}

// ---------------------------------------------------------------------------
// RoPE + scatter
// ---------------------------------------------------------------------------
__global__ __launch_bounds__(256) void rope_scatter_kernel(const float* __restrict__ qkv)
{
    int idx = blockIdx.x * blockDim.x + threadIdx.x;
    if (idx >= SEQ * NH * 32) return;
    int p = idx & 31;
    int h = (idx >> 5) & (NH - 1);
    int l = idx >> 9;

    float inv_freq = powf(10000.0f, -(2.0f * (float)p) / 64.0f);
    float ang = (float)l * inv_freq;
    float s, c;
    sincosf(ang, &s, &c);

    const float* src = qkv + (size_t)l * (3 * DM);
    int col = h * HD + 2 * p;
    float q0 = src[col],          q1 = src[col + 1];
    float k0 = src[DM + col],     k1 = src[DM + col + 1];
    float v0 = src[2 * DM + col], v1 = src[2 * DM + col + 1];

    size_t dst = (size_t)(h * SEQ + l) * HD + 2 * p;
    g_q[dst]     = q0 * c - q1 * s;
    g_q[dst + 1] = q1 * c + q0 * s;
    g_k[dst]     = k0 * c - k1 * s;
    g_k[dst + 1] = k1 * c + k0 * s;
    g_v[dst]     = v0;
    g_v[dst + 1] = v1;
}

// ---------------------------------------------------------------------------
// Tiled flash attention: block = 256 thr = 64-query tile of one head.
// Key tiles of 64, processed DESCENDING from the diagonal.
// Thread (ty,tx): ty=tid>>4 owns queries ty*4+i, tx=tid&15 owns keys/dims tx*4+j.
// Both QK^T and P@V are 4x4-register-tiled GEMMs from smem.
// Smem: Qs (transposed, pre-scaled) + KP union (K transposed / P) + Vs = 48KB.
// ---------------------------------------------------------------------------
__global__ __launch_bounds__(256) void attn_kernel(
    const float* __restrict__ Q, const float* __restrict__ K,
    const float* __restrict__ V, float* __restrict__ O)
{
    __shared__ float Qs[64][64];   // [d][q], prescaled by 1/8
    __shared__ float KP[64][64];   // QK phase: [d][k] ; PV phase: P[q][k]
    __shared__ float Vs[64][64];   // [k][d]

    const int h  = blockIdx.y;
    const int r0 = blockIdx.x * 64;
    const int tid = threadIdx.x;
    const int tx = tid & 15;
    const int ty = tid >> 4;
    const int ty4 = ty * 4;
    const int tx4 = tx * 4;

    // ---- load Q tile, transpose, prescale ----
    {
        const int row  = tid >> 2;
        const int dbase = (tid & 3) * 16;
        const float* qrow = Q + ((size_t)(h * SEQ + r0 + row)) * HD + dbase;
#pragma unroll
        for (int u = 0; u < 4; u++) {
            float4 t4 = *(const float4*)(qrow + 4 * u);
            Qs[dbase + 4 * u + 0][row] = t4.x * 0.125f;
            Qs[dbase + 4 * u + 1][row] = t4.y * 0.125f;
            Qs[dbase + 4 * u + 2][row] = t4.z * 0.125f;
            Qs[dbase + 4 * u + 3][row] = t4.w * 0.125f;
        }
    }

    float o[4][4];
    float m[4], l[4];
#pragma unroll
    for (int i = 0; i < 4; i++) {
        m[i] = -1e30f; l[i] = 0.f;
#pragma unroll
        for (int j = 0; j < 4; j++) o[i][j] = 0.f;
    }

    const int t_hi = r0 >> 6;
    int jmin = r0 - (WIN - 1); if (jmin < 0) jmin = 0;
    const int t_lo = jmin >> 6;

    for (int t = t_hi; t >= t_lo; t--) {
        const int c0 = t * 64;
        __syncthreads();   // previous tile's KP/Vs reads complete

        // ---- load K (transposed) and V tiles ----
        {
            const int row  = tid >> 2;
            const int dbase = (tid & 3) * 16;
            const float* krow = K + ((size_t)(h * SEQ + c0 + row)) * HD + dbase;
            const float* vrow = V + ((size_t)(h * SEQ + c0 + row)) * HD + dbase;
#pragma unroll
            for (int u = 0; u < 4; u++) {
                float4 t4 = *(const float4*)(krow + 4 * u);
                KP[dbase + 4 * u + 0][row] = t4.x;
                KP[dbase + 4 * u + 1][row] = t4.y;
                KP[dbase + 4 * u + 2][row] = t4.z;
                KP[dbase + 4 * u + 3][row] = t4.w;
                *(float4*)(&Vs[row][dbase + 4 * u]) = *(const float4*)(vrow + 4 * u);
            }
        }
        __syncthreads();

        // ---- S = Q @ K^T (4x4 micro-tile) ----
        float s[4][4];
#pragma unroll
        for (int i = 0; i < 4; i++)
#pragma unroll
            for (int j = 0; j < 4; j++) s[i][j] = 0.f;

#pragma unroll 4
        for (int d = 0; d < 64; d++) {
            float a[4], b[4];
            *(float4*)a = *(const float4*)&Qs[d][ty4];
            *(float4*)b = *(const float4*)&KP[d][tx4];
#pragma unroll
            for (int i = 0; i < 4; i++)
#pragma unroll
                for (int j = 0; j < 4; j++)
                    s[i][j] = fmaf(a[i], b[j], s[i][j]);
        }

        // ---- mask (diagonal tile and window-edge tile only) ----
        if (t == t_hi || (t_hi - t) >= 8) {
#pragma unroll
            for (int i = 0; i < 4; i++) {
                int gq = r0 + ty4 + i;
#pragma unroll
                for (int j = 0; j < 4; j++) {
                    int gk = c0 + tx4 + j;
                    bool valid = (gk <= gq) && (gq - gk < WIN);
                    if (!valid) s[i][j] = -1e30f;
                }
            }
        }

        // ---- online softmax (row groups = 16 tx-lanes, shfl reduce) ----
        float p[4][4];
#pragma unroll
        for (int i = 0; i < 4; i++) {
            float mx = fmaxf(fmaxf(s[i][0], s[i][1]), fmaxf(s[i][2], s[i][3]));
#pragma unroll
            for (int off = 8; off >= 1; off >>= 1)
                mx = fmaxf(mx, __shfl_xor_sync(0xFFFFFFFFu, mx, off));
            float newm = fmaxf(m[i], mx);
            float corr = __expf(m[i] - newm);
            float rs = 0.f;
#pragma unroll
            for (int j = 0; j < 4; j++) {
                p[i][j] = __expf(s[i][j] - newm);
                rs += p[i][j];
            }
#pragma unroll
            for (int off = 8; off >= 1; off >>= 1)
                rs += __shfl_xor_sync(0xFFFFFFFFu, rs, off);
            l[i] = l[i] * corr + rs;
            m[i] = newm;
#pragma unroll
            for (int j = 0; j < 4; j++) o[i][j] *= corr;
        }

        __syncthreads();   // all KP (K) reads done; safe to overwrite with P

        // ---- stage P into smem (P[q][k]) ----
#pragma unroll
        for (int i = 0; i < 4; i++)
            *(float4*)&KP[ty4 + i][tx4] = make_float4(p[i][0], p[i][1], p[i][2], p[i][3]);
        __syncthreads();

        // ---- O += P @ V ----
#pragma unroll 4
        for (int k = 0; k < 64; k += 4) {
            float4 b0 = *(const float4*)&Vs[k + 0][tx4];
            float4 b1 = *(const float4*)&Vs[k + 1][tx4];
            float4 b2 = *(const float4*)&Vs[k + 2][tx4];
            float4 b3 = *(const float4*)&Vs[k + 3][tx4];
#pragma unroll
            for (int i = 0; i < 4; i++) {
                float4 a = *(const float4*)&KP[ty4 + i][k];
                o[i][0] = fmaf(a.x, b0.x, o[i][0]);
                o[i][1] = fmaf(a.x, b0.y, o[i][1]);
                o[i][2] = fmaf(a.x, b0.z, o[i][2]);
                o[i][3] = fmaf(a.x, b0.w, o[i][3]);
                o[i][0] = fmaf(a.y, b1.x, o[i][0]);
                o[i][1] = fmaf(a.y, b1.y, o[i][1]);
                o[i][2] = fmaf(a.y, b1.z, o[i][2]);
                o[i][3] = fmaf(a.y, b1.w, o[i][3]);
                o[i][0] = fmaf(a.z, b2.x, o[i][0]);
                o[i][1] = fmaf(a.z, b2.y, o[i][1]);
                o[i][2] = fmaf(a.z, b2.z, o[i][2]);
                o[i][3] = fmaf(a.z, b2.w, o[i][3]);
                o[i][0] = fmaf(a.w, b3.x, o[i][0]);
                o[i][1] = fmaf(a.w, b3.y, o[i][1]);
                o[i][2] = fmaf(a.w, b3.z, o[i][2]);
                o[i][3] = fmaf(a.w, b3.w, o[i][3]);
            }
        }
    }

    // ---- epilogue: normalize and write [L, DM] layout ----
#pragma unroll
    for (int i = 0; i < 4; i++) {
        float inv = 1.0f / l[i];
        float4 r = make_float4(o[i][0] * inv, o[i][1] * inv, o[i][2] * inv, o[i][3] * inv);
        *(float4*)(O + (size_t)(r0 + ty4 + i) * DM + h * HD + tx4) = r;
    }
}

// ---------------------------------------------------------------------------
extern "C" void kernel_launch(void* const* d_in, const int* in_sizes, int n_in,
                              void* d_out, int out_size)
{
    const float* x     = (const float*)d_in[0];
    const float* w_qkv = (const float*)d_in[1];
    const float* w_out = (const float*)d_in[2];
    float* out = (float*)d_out;

    float *p_qkv, *p_q, *p_k, *p_v, *p_att;
    cudaGetSymbolAddress((void**)&p_qkv, g_qkv);
    cudaGetSymbolAddress((void**)&p_q,   g_q);
    cudaGetSymbolAddress((void**)&p_k,   g_k);
    cudaGetSymbolAddress((void**)&p_v,   g_v);
    cudaGetSymbolAddress((void**)&p_att, g_att);

    sgemm_kernel<<<dim3(3 * DM / 128, SEQ / 128), 256>>>(x, w_qkv, p_qkv, SEQ, 3 * DM, DM);

    int total = SEQ * NH * 32;
    rope_scatter_kernel<<<(total + 255) / 256, 256>>>(p_qkv);

    attn_kernel<<<dim3(SEQ / 64, NH), 256>>>(p_q, p_k, p_v, p_att);

    sgemm_kernel<<<dim3(DM / 128, SEQ / 128), 256>>>(p_att, w_out, out, SEQ, DM, DM);
}